// round 8
// baseline (speedup 1.0000x reference)
#include <cuda_runtime.h>

typedef unsigned long long u64;
#define FULLMASK 0xffffffffu
static constexpr float EPSF = 1e-8f;

// ---------- packed f32x2 helpers (sm_103a) ----------
__device__ __forceinline__ u64 pk2(float lo, float hi) {
    u64 d; asm("mov.b64 %0,{%1,%2};" : "=l"(d) : "f"(lo), "f"(hi)); return d;
}
__device__ __forceinline__ float2 upk2(u64 v) {
    float2 o; asm("mov.b64 {%0,%1},%2;" : "=f"(o.x), "=f"(o.y) : "l"(v)); return o;
}
__device__ __forceinline__ u64 fma2_(u64 a, u64 b, u64 c) {
    u64 d; asm("fma.rn.f32x2 %0,%1,%2,%3;" : "=l"(d) : "l"(a), "l"(b), "l"(c)); return d;
}
__device__ __forceinline__ u64 mul2_(u64 a, u64 b) {
    u64 d; asm("mul.rn.f32x2 %0,%1,%2;" : "=l"(d) : "l"(a), "l"(b)); return d;
}
__device__ __forceinline__ u64 add2_(u64 a, u64 b) {
    u64 d; asm("add.rn.f32x2 %0,%1,%2;" : "=l"(d) : "l"(a), "l"(b)); return d;
}
__device__ __forceinline__ u64 splat2(float c) { return pk2(c, c); }

__device__ __forceinline__ float rcp_approx(float x) {
    float r; asm("rcp.approx.f32 %0, %1;" : "=f"(r) : "f"(x)); return r;
}

// butterfly step on a packed f32x2: 2 shuffles + 1 packed add
__device__ __forceinline__ u64 shfl_add2(u64 v, int off) {
    float2 s = upk2(v);
    float ax = __shfl_xor_sync(FULLMASK, s.x, off);
    float ay = __shfl_xor_sync(FULLMASK, s.y, off);
    return add2_(v, pk2(ax, ay));
}

// g(r) = r - sin(2*pi*r)/(2*pi), odd Taylor to r^11 on [-0.5,0.5].
// diff_round(diff_round(x)) = rint(x) + g(g(x - rint(x))).
__device__ __forceinline__ u64 gpoly2(u64 r) {
    u64 z = mul2_(r, r);
    u64 p =            splat2(  2.4023870f);  //  (2pi)^10/11!
    p = fma2_(p, z, splat2( -6.6938470f));    // -(2pi)^8 / 9!
    p = fma2_(p, z, splat2( 12.2081128f));    //  (2pi)^6 / 7!
    p = fma2_(p, z, splat2(-12.9878788f));    // -(2pi)^4 / 5!
    p = fma2_(p, z, splat2(  6.5797363f));    //  (2pi)^2 / 3!
    return mul2_(mul2_(p, z), r);             // r * z * series(z)
}

// mask transform for one float4: m = rint(x) + g(g(x - rint(x))), packed pairs
__device__ __forceinline__ void mask2(float4 mv, u64& m01, u64& m23) {
    float n0 = rintf(mv.x), n1 = rintf(mv.y), n2 = rintf(mv.z), n3 = rintf(mv.w);
    u64 r01 = pk2(mv.x - n0, mv.y - n1);
    u64 r23 = pk2(mv.z - n2, mv.w - n3);
    m01 = add2_(gpoly2(gpoly2(r01)), pk2(n0, n1));
    m23 = add2_(gpoly2(gpoly2(r23)), pk2(n2, n3));
}

__global__ void zero_out_kernel(float* out, int n) {
    int i = blockIdx.x * blockDim.x + threadIdx.x;
    if (i < n) out[i] = 0.0f;
}

// One quad (4 areas) of work for this lane; accumulates into acc2.
__device__ __forceinline__ void do_quad(
    float4 iv0, float4 iv1, float4 mv0, float4 mv1, u64& acc2)
{
    u64 m01, m23, m45, m67;
    mask2(mv0, m01, m23);
    mask2(mv1, m45, m67);

    u64 t01 = mul2_(pk2(iv0.x, iv0.y), m01);
    u64 t23 = mul2_(pk2(iv0.z, iv0.w), m23);
    u64 t45 = mul2_(pk2(iv1.x, iv1.y), m45);
    u64 t67 = mul2_(pk2(iv1.z, iv1.w), m67);

    u64 u01 = mul2_(m01, t01), u23 = mul2_(m23, t23);
    u64 u45 = mul2_(m45, t45), u67 = mul2_(m67, t67);

    // per-lane linear statistics (stay local; no cross-lane reduction)
    u64 A2 = mul2_(u01, u01);
    A2 = fma2_(u23, u23, A2); A2 = fma2_(u45, u45, A2); A2 = fma2_(u67, u67, A2);
    u64 B2 = mul2_(m01, u01);
    B2 = fma2_(m23, u23, B2); B2 = fma2_(m45, u45, B2); B2 = fma2_(m67, u67, B2);
    u64 C2 = mul2_(m01, m01);
    C2 = fma2_(m23, m23, C2); C2 = fma2_(m45, m45, C2); C2 = fma2_(m67, m67, C2);

    // only (sum_m, sum_t) crosses lanes: one joint 3-step butterfly
    float2 pm = upk2(add2_(add2_(m01, m23), add2_(m45, m67)));
    float2 pt = upk2(add2_(add2_(t01, t23), add2_(t45, t67)));
    u64 red = pk2(pm.x + pm.y, pt.x + pt.y);
    red = shfl_add2(red, 4);
    red = shfl_add2(red, 2);
    red = shfl_add2(red, 1);
    float2 sums = upk2(red);            // x = sum_m, y = sum_t (uniform/octet)

    float rinv = rcp_approx(sums.x + EPSF);
    float mean = sums.y * rinv;

    // lane contribution: (A - 2*mean*B + mean^2*C) * rinv
    u64 w2 = fma2_(splat2(mean), C2, mul2_(splat2(-2.0f), B2));
    u64 c2 = fma2_(splat2(mean), w2, A2);
    acc2 = fma2_(c2, splat2(rinv), acc2);
}

// 8 lanes per area, 8 elems/lane, warp covers 4 areas (one quad) per unit.
// Chunks of 2 quads (8 batched LDG.128) + 64-reg cap -> occupancy ~50%,
// 2 loop trips per warp allow cross-trip load/compute overlap.
__global__ __launch_bounds__(256, 4) void area_loss_kernel(
    const float4* __restrict__ img4,
    const float4* __restrict__ msk4,
    float* __restrict__ out,
    int nQuads, float invTotal)
{
    __shared__ float bsum;
    if (threadIdx.x == 0) bsum = 0.0f;
    __syncthreads();

    const int lane = threadIdx.x & 31;
    const int q    = lane & 7;         // lane within octet
    const int oct  = lane >> 3;        // which area of the quad
    const int warpId = (blockIdx.x * blockDim.x + threadIdx.x) >> 5;
    const int nWarps = (gridDim.x * blockDim.x) >> 5;

    u64 acc2 = 0;                      // packed per-lane accumulator

    int w0 = warpId * 2;
    const int stride = nWarps * 2;

    for (; w0 + 1 < nQuads; w0 += stride) {
        // ---- batched load phase: 8 independent 16B loads ----
        float4 IV[2][2], MV[2][2];
        #pragma unroll
        for (int j = 0; j < 2; j++) {
            const int a    = 4 * (w0 + j) + oct;
            const int base = a * 16 + q * 2;
            IV[j][0] = img4[base];  IV[j][1] = img4[base + 1];
            MV[j][0] = msk4[base];  MV[j][1] = msk4[base + 1];
        }
        // ---- compute phase: 2 independent chains ----
        #pragma unroll
        for (int j = 0; j < 2; j++)
            do_quad(IV[j][0], IV[j][1], MV[j][0], MV[j][1], acc2);
    }
    // tail (not taken for the benchmark shape)
    for (int w = w0; w < nQuads; w++) {
        const int a    = 4 * w + oct;
        const int base = a * 16 + q * 2;
        do_quad(img4[base], img4[base + 1], msk4[base], msk4[base + 1], acc2);
    }

    // epilogue: collapse packed lanes, full-warp butterfly, one atomic/block
    float2 ap = upk2(acc2);
    float acc = ap.x + ap.y;
    #pragma unroll
    for (int o = 16; o > 0; o >>= 1)
        acc += __shfl_xor_sync(FULLMASK, acc, o);
    if (lane == 0) atomicAdd(&bsum, acc);
    __syncthreads();
    if (threadIdx.x == 0) atomicAdd(out, bsum * invTotal);
}

extern "C" void kernel_launch(void* const* d_in, const int* in_sizes, int n_in,
                              void* d_out, int out_size)
{
    const float4* img4 = (const float4*)d_in[0];  // sv_area_image
    const float4* msk4 = (const float4*)d_in[1];  // sv_area_mask
    float* out = (float*)d_out;

    const int nAreas = in_sizes[0] / 64;          // B*N areas of 8x8
    const int nQuads = nAreas / 4;
    const float invTotal = 1.0f / (float)nAreas;

    zero_out_kernel<<<(out_size + 255) / 256, 256>>>(out, out_size);

    area_loss_kernel<<<1024, 256>>>(img4, msk4, out, nQuads, invTotal);
}

// round 9
// speedup vs baseline: 1.0194x; 1.0194x over previous
#include <cuda_runtime.h>

typedef unsigned long long u64;
#define FULLMASK 0xffffffffu
static constexpr float EPSF = 1e-8f;

// ---------- packed f32x2 helpers (sm_103a) ----------
__device__ __forceinline__ u64 pk2(float lo, float hi) {
    u64 d; asm("mov.b64 %0,{%1,%2};" : "=l"(d) : "f"(lo), "f"(hi)); return d;
}
__device__ __forceinline__ float2 upk2(u64 v) {
    float2 o; asm("mov.b64 {%0,%1},%2;" : "=f"(o.x), "=f"(o.y) : "l"(v)); return o;
}
__device__ __forceinline__ u64 fma2_(u64 a, u64 b, u64 c) {
    u64 d; asm("fma.rn.f32x2 %0,%1,%2,%3;" : "=l"(d) : "l"(a), "l"(b), "l"(c)); return d;
}
__device__ __forceinline__ u64 mul2_(u64 a, u64 b) {
    u64 d; asm("mul.rn.f32x2 %0,%1,%2;" : "=l"(d) : "l"(a), "l"(b)); return d;
}
__device__ __forceinline__ u64 add2_(u64 a, u64 b) {
    u64 d; asm("add.rn.f32x2 %0,%1,%2;" : "=l"(d) : "l"(a), "l"(b)); return d;
}
__device__ __forceinline__ u64 splat2(float c) { return pk2(c, c); }

__device__ __forceinline__ float rcp_approx(float x) {
    float r; asm("rcp.approx.f32 %0, %1;" : "=f"(r) : "f"(x)); return r;
}

// butterfly step on a packed f32x2: 2 shuffles + 1 packed add
__device__ __forceinline__ u64 shfl_add2(u64 v, int off) {
    float2 s = upk2(v);
    float ax = __shfl_xor_sync(FULLMASK, s.x, off);
    float ay = __shfl_xor_sync(FULLMASK, s.y, off);
    return add2_(v, pk2(ax, ay));
}

// g(r) = r - sin(2*pi*r)/(2*pi), odd Taylor to r^11 on [-0.5,0.5].
// diff_round(diff_round(x)) = rint(x) + g(g(x - rint(x))).
__device__ __forceinline__ u64 gpoly2(u64 r) {
    u64 z = mul2_(r, r);
    u64 p =            splat2(  2.4023870f);  //  (2pi)^10/11!
    p = fma2_(p, z, splat2( -6.6938470f));    // -(2pi)^8 / 9!
    p = fma2_(p, z, splat2( 12.2081128f));    //  (2pi)^6 / 7!
    p = fma2_(p, z, splat2(-12.9878788f));    // -(2pi)^4 / 5!
    p = fma2_(p, z, splat2(  6.5797363f));    //  (2pi)^2 / 3!
    return mul2_(mul2_(p, z), r);             // r * z * series(z)
}

// mask transform for one float4: m = rint(x) + g(g(x - rint(x))), packed pairs
__device__ __forceinline__ void mask2(float4 mv, u64& m01, u64& m23) {
    float n0 = rintf(mv.x), n1 = rintf(mv.y), n2 = rintf(mv.z), n3 = rintf(mv.w);
    u64 r01 = pk2(mv.x - n0, mv.y - n1);
    u64 r23 = pk2(mv.z - n2, mv.w - n3);
    m01 = add2_(gpoly2(gpoly2(r01)), pk2(n0, n1));
    m23 = add2_(gpoly2(gpoly2(r23)), pk2(n2, n3));
}

__global__ void zero_out_kernel(float* out, int n) {
    int i = blockIdx.x * blockDim.x + threadIdx.x;
    if (i < n) out[i] = 0.0f;
}

// One quad (4 areas) of work for this lane; accumulates into acc2.
// Element order within a lane is irrelevant (sums only).
__device__ __forceinline__ void do_quad(
    float4 iv0, float4 iv1, float4 mv0, float4 mv1, u64& acc2)
{
    u64 m01, m23, m45, m67;
    mask2(mv0, m01, m23);
    mask2(mv1, m45, m67);

    u64 t01 = mul2_(pk2(iv0.x, iv0.y), m01);
    u64 t23 = mul2_(pk2(iv0.z, iv0.w), m23);
    u64 t45 = mul2_(pk2(iv1.x, iv1.y), m45);
    u64 t67 = mul2_(pk2(iv1.z, iv1.w), m67);

    u64 u01 = mul2_(m01, t01), u23 = mul2_(m23, t23);
    u64 u45 = mul2_(m45, t45), u67 = mul2_(m67, t67);

    // per-lane linear statistics (stay local; no cross-lane reduction)
    u64 A2 = mul2_(u01, u01);
    A2 = fma2_(u23, u23, A2); A2 = fma2_(u45, u45, A2); A2 = fma2_(u67, u67, A2);
    u64 B2 = mul2_(m01, u01);
    B2 = fma2_(m23, u23, B2); B2 = fma2_(m45, u45, B2); B2 = fma2_(m67, u67, B2);
    u64 C2 = mul2_(m01, m01);
    C2 = fma2_(m23, m23, C2); C2 = fma2_(m45, m45, C2); C2 = fma2_(m67, m67, C2);

    // only (sum_m, sum_t) crosses lanes: one joint 3-step butterfly
    float2 pm = upk2(add2_(add2_(m01, m23), add2_(m45, m67)));
    float2 pt = upk2(add2_(add2_(t01, t23), add2_(t45, t67)));
    u64 red = pk2(pm.x + pm.y, pt.x + pt.y);
    red = shfl_add2(red, 4);
    red = shfl_add2(red, 2);
    red = shfl_add2(red, 1);
    float2 sums = upk2(red);            // x = sum_m, y = sum_t (uniform/octet)

    float rinv = rcp_approx(sums.x + EPSF);
    float mean = sums.y * rinv;

    // lane contribution: (A - 2*mean*B + mean^2*C) * rinv
    u64 w2 = fma2_(splat2(mean), C2, mul2_(splat2(-2.0f), B2));
    u64 c2 = fma2_(splat2(mean), w2, A2);
    acc2 = fma2_(c2, splat2(rinv), acc2);
}

// 8 lanes per area, 8 elems/lane (float4 at q and q+8 -> each warp load
// instruction covers 4 FULL 128B lines = minimal L1 wavefronts).
// Chunks of 2 quads; grid = one exact wave at occupancy 4 blocks/SM.
__global__ __launch_bounds__(256, 4) void area_loss_kernel(
    const float4* __restrict__ img4,
    const float4* __restrict__ msk4,
    float* __restrict__ out,
    int nQuads, float invTotal)
{
    __shared__ float bsum;
    if (threadIdx.x == 0) bsum = 0.0f;
    __syncthreads();

    const int lane = threadIdx.x & 31;
    const int q    = lane & 7;         // lane within octet
    const int oct  = lane >> 3;        // which area of the quad
    const int warpId = (blockIdx.x * blockDim.x + threadIdx.x) >> 5;
    const int nWarps = (gridDim.x * blockDim.x) >> 5;

    u64 acc2 = 0;                      // packed per-lane accumulator

    int w0 = warpId * 2;
    const int stride = nWarps * 2;

    for (; w0 + 1 < nQuads; w0 += stride) {
        // ---- batched load phase: 8 independent 16B loads, fully coalesced ----
        float4 IV[2][2], MV[2][2];
        #pragma unroll
        for (int j = 0; j < 2; j++) {
            const int base = (4 * (w0 + j) + oct) * 16 + q;   // float4 index
            IV[j][0] = img4[base];  IV[j][1] = img4[base + 8];
            MV[j][0] = msk4[base];  MV[j][1] = msk4[base + 8];
        }
        // ---- compute phase: 2 independent chains ----
        #pragma unroll
        for (int j = 0; j < 2; j++)
            do_quad(IV[j][0], IV[j][1], MV[j][0], MV[j][1], acc2);
    }
    // tail
    for (int w = w0; w < nQuads; w++) {
        const int base = (4 * w + oct) * 16 + q;
        do_quad(img4[base], img4[base + 8], msk4[base], msk4[base + 8], acc2);
    }

    // epilogue: collapse packed lanes, full-warp butterfly, one atomic/block
    float2 ap = upk2(acc2);
    float acc = ap.x + ap.y;
    #pragma unroll
    for (int o = 16; o > 0; o >>= 1)
        acc += __shfl_xor_sync(FULLMASK, acc, o);
    if (lane == 0) atomicAdd(&bsum, acc);
    __syncthreads();
    if (threadIdx.x == 0) atomicAdd(out, bsum * invTotal);
}

extern "C" void kernel_launch(void* const* d_in, const int* in_sizes, int n_in,
                              void* d_out, int out_size)
{
    const float4* img4 = (const float4*)d_in[0];  // sv_area_image
    const float4* msk4 = (const float4*)d_in[1];  // sv_area_mask
    float* out = (float*)d_out;

    const int nAreas = in_sizes[0] / 64;          // B*N areas of 8x8
    const int nQuads = nAreas / 4;
    const float invTotal = 1.0f / (float)nAreas;

    zero_out_kernel<<<(out_size + 255) / 256, 256>>>(out, out_size);

    // 148 SMs x 4 blocks = exactly one full wave at occupancy 4
    area_loss_kernel<<<592, 256>>>(img4, msk4, out, nQuads, invTotal);
}